// round 4
// baseline (speedup 1.0000x reference)
#include <cuda_runtime.h>
#include <cstdint>

// Problem dims
#define B_  2
#define Qn  2048
#define Sn  2048
#define Dn  1024
#define Hn  16
#define AD  64
#define MQ  (B_ * Qn)   // 4096 rows for Q-side GEMMs
#define MS  (B_ * Sn)   // 4096 rows for KV GEMM

// Scratch (allocation-free rule: __device__ globals)
__device__ float g_rq[(size_t)MQ * Dn];        // (B,Q,H,AD) = (4096,1024)
__device__ float g_kv[(size_t)MS * 2 * Dn];    // (B,S,2,H,AD) = (4096,2048)
__device__ float g_o [(size_t)MQ * Dn];        // (B,Q,H,AD)

// ---------------------------------------------------------------------------
// Generic SGEMM: Out[m,n] = sum_k X[m,k] * W[n,k]   (i.e. X @ W^T)
// Tiles: 128x128x16, 256 threads, 8x8 per thread. M,N,K multiples of 128/16.
// ---------------------------------------------------------------------------
__global__ __launch_bounds__(256)
void gemm_xwt(const float* __restrict__ X, const float* __restrict__ W,
              float* __restrict__ Out, int M, int N, int K) {
    __shared__ float As[16 * 129];   // As[k][m], padded
    __shared__ float Bs[16 * 129];   // Bs[k][n], padded

    const int tid = threadIdx.x;
    const int ty  = tid >> 4;        // 0..15 -> rows ty*8
    const int tx  = tid & 15;        // 0..15 -> cols tx*8
    const int m0  = blockIdx.y * 128;
    const int n0  = blockIdx.x * 128;

    const int lr = tid >> 1;         // 0..127
    const int lk = (tid & 1) * 8;    // 0 or 8
    const float* Xp = X + (size_t)(m0 + lr) * K + lk;
    const float* Wp = W + (size_t)(n0 + lr) * K + lk;

    float acc[8][8] = {};

    for (int k0 = 0; k0 < K; k0 += 16) {
        float4 a0 = *(const float4*)(Xp + k0);
        float4 a1 = *(const float4*)(Xp + k0 + 4);
        float4 b0 = *(const float4*)(Wp + k0);
        float4 b1 = *(const float4*)(Wp + k0 + 4);
        __syncthreads();
        As[(lk+0)*129+lr]=a0.x; As[(lk+1)*129+lr]=a0.y; As[(lk+2)*129+lr]=a0.z; As[(lk+3)*129+lr]=a0.w;
        As[(lk+4)*129+lr]=a1.x; As[(lk+5)*129+lr]=a1.y; As[(lk+6)*129+lr]=a1.z; As[(lk+7)*129+lr]=a1.w;
        Bs[(lk+0)*129+lr]=b0.x; Bs[(lk+1)*129+lr]=b0.y; Bs[(lk+2)*129+lr]=b0.z; Bs[(lk+3)*129+lr]=b0.w;
        Bs[(lk+4)*129+lr]=b1.x; Bs[(lk+5)*129+lr]=b1.y; Bs[(lk+6)*129+lr]=b1.z; Bs[(lk+7)*129+lr]=b1.w;
        __syncthreads();
        #pragma unroll
        for (int k = 0; k < 16; k++) {
            float ar[8], br[8];
            #pragma unroll
            for (int i = 0; i < 8; i++) ar[i] = As[k*129 + ty*8 + i];
            #pragma unroll
            for (int j = 0; j < 8; j++) br[j] = Bs[k*129 + tx*8 + j];
            #pragma unroll
            for (int i = 0; i < 8; i++)
                #pragma unroll
                for (int j = 0; j < 8; j++)
                    acc[i][j] += ar[i] * br[j];
        }
    }

    #pragma unroll
    for (int i = 0; i < 8; i++) {
        float* op = Out + (size_t)(m0 + ty*8 + i) * N + n0 + tx*8;
        *(float4*)(op)     = make_float4(acc[i][0], acc[i][1], acc[i][2], acc[i][3]);
        *(float4*)(op + 4) = make_float4(acc[i][4], acc[i][5], acc[i][6], acc[i][7]);
    }
}

// ---------------------------------------------------------------------------
// Fused attention: per block = 128 q-rows x 1 head. Loop S in 64-wide tiles.
// t = mask ? 0 : relu(score/8 + nbias)^2 ; o += t @ V ; denom += rowsum(t)
// Final: o /= denom (+1e-32). No softmax max-tracking needed (relu^2 norm).
// ---------------------------------------------------------------------------
#define ATTN_SMEM ((128 + 64 + 64 + 128) * 65 * 4)   // Qs,Ks,Vs,Ts -> 99840 B

__global__ __launch_bounds__(256, 2)
void attn_kernel(const float* __restrict__ rq, const float* __restrict__ kvb,
                 const int* __restrict__ mask,
                 const float* __restrict__ nbias,
                 float* __restrict__ o) {
    extern __shared__ float sm[];
    float* Qs = sm;                  // [128][65]  (q x d)
    float* Ks = Qs + 128 * 65;       // [64][65]   (s x d)
    float* Vs = Ks + 64 * 65;        // [64][65]   (s x d)
    float* Ts = Vs + 64 * 65;        // [128][65]  (q x s)

    const int tid = threadIdx.x;
    const int ty  = tid >> 4;        // 0..15 -> q rows ty*8
    const int tx  = tid & 15;        // 0..15 -> s/d cols tx*4
    const int b   = blockIdx.y >> 4;
    const int h   = blockIdx.y & 15;
    const int q0  = blockIdx.x * 128;
    const float nb = nbias[0];

    // Load Q tile (128 x 64): 2 threads per row, 32 floats each
    {
        int lr = tid >> 1;
        int d0 = (tid & 1) * 32;
        const float* src = rq + ((size_t)(b * Qn + q0 + lr) * Hn + h) * AD + d0;
        #pragma unroll
        for (int j = 0; j < 8; j++) {
            float4 v = *(const float4*)(src + j * 4);
            int d = d0 + j * 4;
            Qs[lr*65+d]=v.x; Qs[lr*65+d+1]=v.y; Qs[lr*65+d+2]=v.z; Qs[lr*65+d+3]=v.w;
        }
    }

    float oacc[8][4] = {};
    float rs[8] = {};
    const int* mrow = mask + (size_t)b * Qn * Sn + (size_t)q0 * Sn;

    for (int s0 = 0; s0 < Sn; s0 += 64) {
        __syncthreads();   // prev iter done reading Ks/Vs/Ts
        // Load K,V tiles (64 x 64 each): 4 threads per row, 16 floats each
        {
            int lr = tid >> 2;
            int d0 = (tid & 3) * 16;
            const float* kb = kvb + (size_t)(b * Sn + s0 + lr) * (2 * Dn) + h * AD + d0;
            #pragma unroll
            for (int j = 0; j < 4; j++) {
                int d = d0 + j * 4;
                float4 kk = *(const float4*)(kb + j * 4);
                Ks[lr*65+d]=kk.x; Ks[lr*65+d+1]=kk.y; Ks[lr*65+d+2]=kk.z; Ks[lr*65+d+3]=kk.w;
                float4 vv = *(const float4*)(kb + Dn + j * 4);
                Vs[lr*65+d]=vv.x; Vs[lr*65+d+1]=vv.y; Vs[lr*65+d+2]=vv.z; Vs[lr*65+d+3]=vv.w;
            }
        }
        __syncthreads();

        // scores: 128x64 tile, thread computes 8x4
        float sacc[8][4] = {};
        #pragma unroll 8
        for (int k = 0; k < AD; k++) {
            float ar[8], br[4];
            #pragma unroll
            for (int i = 0; i < 8; i++) ar[i] = Qs[(ty*8+i)*65 + k];
            #pragma unroll
            for (int j = 0; j < 4; j++) br[j] = Ks[(tx*4+j)*65 + k];
            #pragma unroll
            for (int i = 0; i < 8; i++)
                #pragma unroll
                for (int j = 0; j < 4; j++)
                    sacc[i][j] += ar[i] * br[j];
        }

        // epilogue: mask + relu^2, stash to Ts, accumulate row sums
        #pragma unroll
        for (int i = 0; i < 8; i++) {
            const int* mp = mrow + (size_t)(ty*8+i) * Sn + s0 + tx*4;
            int4 mv = *(const int4*)mp;
            #pragma unroll
            for (int j = 0; j < 4; j++) {
                int m = (j == 0) ? mv.x : (j == 1) ? mv.y : (j == 2) ? mv.z : mv.w;
                float t = sacc[i][j] * 0.125f + nb;
                t = m ? 0.0f : fmaxf(t, 0.0f);
                t = t * t;
                rs[i] += t;
                Ts[(ty*8+i)*65 + tx*4 + j] = t;
            }
        }
        __syncthreads();

        // o += Ts(128x64) @ Vs(64x64), thread computes 8x4
        #pragma unroll 8
        for (int k = 0; k < 64; k++) {
            float tr[8], vr[4];
            #pragma unroll
            for (int i = 0; i < 8; i++) tr[i] = Ts[(ty*8+i)*65 + k];
            #pragma unroll
            for (int j = 0; j < 4; j++) vr[j] = Vs[k*65 + tx*4 + j];
            #pragma unroll
            for (int i = 0; i < 8; i++)
                #pragma unroll
                for (int j = 0; j < 4; j++)
                    oacc[i][j] += tr[i] * vr[j];
        }
    }

    __syncthreads();
    // Row-sum reduction across the 16 tx lanes (reuse Ks as [128][16])
    #pragma unroll
    for (int i = 0; i < 8; i++) Ks[(ty*8+i)*16 + tx] = rs[i];
    __syncthreads();
    if (tid < 128) {
        float d = 1e-32f;
        #pragma unroll
        for (int t = 0; t < 16; t++) d += Ks[tid*16 + t];
        Vs[tid] = d;   // reuse Vs[0..127] as denom
    }
    __syncthreads();

    #pragma unroll
    for (int i = 0; i < 8; i++) {
        float inv = 1.0f / Vs[ty*8 + i];
        float* op = o + ((size_t)(b * Qn + q0 + ty*8 + i) * Hn + h) * AD + tx*4;
        op[0] = oacc[i][0] * inv;
        op[1] = oacc[i][1] * inv;
        op[2] = oacc[i][2] * inv;
        op[3] = oacc[i][3] * inv;
    }
}

// ---------------------------------------------------------------------------
extern "C" void kernel_launch(void* const* d_in, const int* in_sizes, int n_in,
                              void* d_out, int out_size) {
    const float* iQ    = (const float*)d_in[0];
    const float* iK    = (const float*)d_in[1];
    const int*   mask  = (const int*)d_in[2];
    const float* Wq    = (const float*)d_in[3];
    const float* Wkv   = (const float*)d_in[4];
    const float* Wo    = (const float*)d_in[5];
    const float* nbias = (const float*)d_in[6];
    float* out = (float*)d_out;

    float *rq, *kvb, *ob;
    cudaGetSymbolAddress((void**)&rq,  g_rq);
    cudaGetSymbolAddress((void**)&kvb, g_kv);
    cudaGetSymbolAddress((void**)&ob,  g_o);

    // 1) Projections
    gemm_xwt<<<dim3(Dn/128,   MQ/128), 256>>>(iQ, Wq,  rq,  MQ, Dn,   Dn);
    gemm_xwt<<<dim3(2*Dn/128, MS/128), 256>>>(iK, Wkv, kvb, MS, 2*Dn, Dn);

    // 2) Attention
    cudaFuncSetAttribute(attn_kernel, cudaFuncAttributeMaxDynamicSharedMemorySize, ATTN_SMEM);
    attn_kernel<<<dim3(Qn/128, B_*Hn), 256, ATTN_SMEM>>>(rq, kvb, mask, nbias, ob);

    // 3) Output projection
    gemm_xwt<<<dim3(Dn/128, MQ/128), 256>>>(ob, Wo, out, MQ, Dn, Dn);
}

// round 8
// speedup vs baseline: 1.3997x; 1.3997x over previous
#include <cuda_runtime.h>
#include <cuda_bf16.h>
#include <cstdint>

// Problem dims
#define B_  2
#define Qn  2048
#define Sn  2048
#define Dn  1024
#define Hn  16
#define AD  64
#define MQ  (B_ * Qn)   // 4096
#define MS  (B_ * Sn)   // 4096

// ---------------- scratch (__device__ globals; no allocs allowed) ----------
__device__ float g_rq[(size_t)MQ * Dn];
__device__ float g_kv[(size_t)MS * 2 * Dn];
__device__ float g_o [(size_t)MQ * Dn];

__device__ __nv_bfloat16 g_xq_h[(size_t)MQ * Dn],  g_xq_l[(size_t)MQ * Dn];
__device__ __nv_bfloat16 g_xk_h[(size_t)MS * Dn],  g_xk_l[(size_t)MS * Dn];
__device__ __nv_bfloat16 g_ob_h[(size_t)MQ * Dn],  g_ob_l[(size_t)MQ * Dn];
__device__ __nv_bfloat16 g_wq_h[(size_t)Dn * Dn],  g_wq_l[(size_t)Dn * Dn];
__device__ __nv_bfloat16 g_wkv_h[(size_t)2 * Dn * Dn], g_wkv_l[(size_t)2 * Dn * Dn];
__device__ __nv_bfloat16 g_wo_h[(size_t)Dn * Dn],  g_wo_l[(size_t)Dn * Dn];

// ---------------- warp-MMA helpers (sm_80+ PTX, family-portable) -----------
__device__ __forceinline__ uint32_t smem_u32(const void* p) {
    uint32_t a;
    asm("{ .reg .u64 t; cvta.to.shared.u64 t, %1; cvt.u32.u64 %0, t; }" : "=r"(a) : "l"(p));
    return a;
}
__device__ __forceinline__ void ldsm_x4(uint32_t& r0, uint32_t& r1, uint32_t& r2,
                                        uint32_t& r3, uint32_t addr) {
    asm volatile("ldmatrix.sync.aligned.m8n8.x4.shared.b16 {%0,%1,%2,%3}, [%4];"
                 : "=r"(r0), "=r"(r1), "=r"(r2), "=r"(r3) : "r"(addr));
}
__device__ __forceinline__ void ldsm_x2(uint32_t& r0, uint32_t& r1, uint32_t addr) {
    asm volatile("ldmatrix.sync.aligned.m8n8.x2.shared.b16 {%0,%1}, [%2];"
                 : "=r"(r0), "=r"(r1) : "r"(addr));
}
__device__ __forceinline__ void mma16816(float* d, const uint32_t* a, const uint32_t* b) {
    asm volatile("mma.sync.aligned.m16n8k16.row.col.f32.bf16.bf16.f32 "
                 "{%0,%1,%2,%3}, {%4,%5,%6,%7}, {%8,%9}, {%0,%1,%2,%3};"
                 : "+f"(d[0]), "+f"(d[1]), "+f"(d[2]), "+f"(d[3])
                 : "r"(a[0]), "r"(a[1]), "r"(a[2]), "r"(a[3]), "r"(b[0]), "r"(b[1]));
}

// ---------------------------------------------------------------------------
// fp32 -> (hi, lo) bf16 split:  x = hi + lo, lo = bf16(x - hi)
// ---------------------------------------------------------------------------
__global__ __launch_bounds__(256)
void cvt_split(const float* __restrict__ x, __nv_bfloat16* __restrict__ h,
               __nv_bfloat16* __restrict__ l, int n) {
    int i = (blockIdx.x * 256 + threadIdx.x) * 4;
    if (i >= n) return;
    float4 v = *(const float4*)(x + i);
    __nv_bfloat16 h0 = __float2bfloat16(v.x), h1 = __float2bfloat16(v.y);
    __nv_bfloat16 h2 = __float2bfloat16(v.z), h3 = __float2bfloat16(v.w);
    __nv_bfloat16 l0 = __float2bfloat16(v.x - __bfloat162float(h0));
    __nv_bfloat16 l1 = __float2bfloat16(v.y - __bfloat162float(h1));
    __nv_bfloat16 l2 = __float2bfloat16(v.z - __bfloat162float(h2));
    __nv_bfloat16 l3 = __float2bfloat16(v.w - __bfloat162float(h3));
    ((__nv_bfloat162*)(h + i))[0] = __nv_bfloat162(h0, h1);
    ((__nv_bfloat162*)(h + i))[1] = __nv_bfloat162(h2, h3);
    ((__nv_bfloat162*)(l + i))[0] = __nv_bfloat162(l0, l1);
    ((__nv_bfloat162*)(l + i))[1] = __nv_bfloat162(l2, l3);
}

// ---------------------------------------------------------------------------
// Split-bf16 warp-MMA GEMM:  Out[m,n] = sum_k A[m,k]*B[n,k]  (X @ W^T)
// D += Ah*Bh + Ah*Bl + Al*Bh  (fp32 accum). CTA 128x128, K-chunk 64.
// 8 warps (2x4), warp tile 64x32, m16n8k16 atoms via ldmatrix.
// smem rows padded to 72 bf16 (144 B) -> conflict-free ldmatrix.
// ---------------------------------------------------------------------------
#define KC   64
#define LDS  72
#define TILE_B (128 * LDS * 2)          // 18432 B per tile
#define GEMM_SMEM (4 * TILE_B)          // 73728 B

__global__ __launch_bounds__(256)
void gemm_mma_split(const __nv_bfloat16* __restrict__ Ah, const __nv_bfloat16* __restrict__ Al,
                    const __nv_bfloat16* __restrict__ Bh, const __nv_bfloat16* __restrict__ Bl,
                    float* __restrict__ Out, int M, int N, int K) {
    extern __shared__ char smc[];
    __nv_bfloat16* sAh = (__nv_bfloat16*)smc;
    __nv_bfloat16* sAl = sAh + 128 * LDS;
    __nv_bfloat16* sBh = sAl + 128 * LDS;
    __nv_bfloat16* sBl = sBh + 128 * LDS;

    const int tid  = threadIdx.x;
    const int lane = tid & 31;
    const int wid  = tid >> 5;
    const int wm   = wid >> 2;          // 0..1  -> 64-row strip
    const int wn   = wid & 3;           // 0..3  -> 32-col strip
    const int m0   = blockIdx.y * 128;
    const int n0   = blockIdx.x * 128;
    const uint32_t sb = smem_u32(smc);

    float acc[4][4][4] = {};

    // ldmatrix per-lane offsets (bytes, within a tile)
    const uint32_t aoff = ((uint32_t)((lane & 15) * LDS) + (lane >> 4) * 8) * 2;
    const uint32_t boff = ((uint32_t)((lane & 7) * LDS) + ((lane >> 3) & 1) * 8) * 2;

    for (int k0 = 0; k0 < K; k0 += KC) {
        // cooperative gmem -> smem (4 tiles, 16B per thread per pass)
        #pragma unroll
        for (int i = 0; i < 4; i++) {
            const int linear = i * 256 + tid;
            const int row = linear >> 3;
            const int c   = (linear & 7) * 8;
            const size_t ga = (size_t)(m0 + row) * K + k0 + c;
            const size_t gb = (size_t)(n0 + row) * K + k0 + c;
            *(uint4*)(sAh + row * LDS + c) = *(const uint4*)(Ah + ga);
            *(uint4*)(sAl + row * LDS + c) = *(const uint4*)(Al + ga);
            *(uint4*)(sBh + row * LDS + c) = *(const uint4*)(Bh + gb);
            *(uint4*)(sBl + row * LDS + c) = *(const uint4*)(Bl + gb);
        }
        __syncthreads();

        #pragma unroll
        for (int ks = 0; ks < KC / 16; ks++) {
            const uint32_t kso = (uint32_t)(ks * 16 * 2);
            uint32_t ah[4][4], al[4][4], bh[4][2], bl[4][2];
            #pragma unroll
            for (int mt = 0; mt < 4; mt++) {
                const uint32_t o = (uint32_t)((wm * 64 + mt * 16) * LDS * 2) + aoff + kso;
                ldsm_x4(ah[mt][0], ah[mt][1], ah[mt][2], ah[mt][3], sb + o);
                ldsm_x4(al[mt][0], al[mt][1], al[mt][2], al[mt][3], sb + TILE_B + o);
            }
            #pragma unroll
            for (int nt = 0; nt < 4; nt++) {
                const uint32_t o = (uint32_t)((wn * 32 + nt * 8) * LDS * 2) + boff + kso;
                ldsm_x2(bh[nt][0], bh[nt][1], sb + 2 * TILE_B + o);
                ldsm_x2(bl[nt][0], bl[nt][1], sb + 3 * TILE_B + o);
            }
            #pragma unroll
            for (int mt = 0; mt < 4; mt++)
                #pragma unroll
                for (int nt = 0; nt < 4; nt++) {
                    mma16816(acc[mt][nt], ah[mt], bh[nt]);
                    mma16816(acc[mt][nt], ah[mt], bl[nt]);
                    mma16816(acc[mt][nt], al[mt], bh[nt]);
                }
        }
        __syncthreads();
    }

    // epilogue: fragment layout m16n8 -> rows (lane>>2, +8), cols (lane&3)*2
    #pragma unroll
    for (int mt = 0; mt < 4; mt++) {
        const int m = m0 + wm * 64 + mt * 16 + (lane >> 2);
        #pragma unroll
        for (int nt = 0; nt < 4; nt++) {
            const int n = n0 + wn * 32 + nt * 8 + (lane & 3) * 2;
            *(float2*)(Out + (size_t)m * N + n)       = make_float2(acc[mt][nt][0], acc[mt][nt][1]);
            *(float2*)(Out + (size_t)(m + 8) * N + n) = make_float2(acc[mt][nt][2], acc[mt][nt][3]);
        }
    }
}

// ---------------------------------------------------------------------------
// Fused attention (unchanged, passing at R4): 128 q-rows x 1 head per block.
// ---------------------------------------------------------------------------
#define ATTN_SMEM ((128 + 64 + 64 + 128) * 65 * 4)

__global__ __launch_bounds__(256, 2)
void attn_kernel(const float* __restrict__ rq, const float* __restrict__ kvb,
                 const int* __restrict__ mask,
                 const float* __restrict__ nbias,
                 float* __restrict__ o) {
    extern __shared__ float sm[];
    float* Qs = sm;
    float* Ks = Qs + 128 * 65;
    float* Vs = Ks + 64 * 65;
    float* Ts = Vs + 64 * 65;

    const int tid = threadIdx.x;
    const int ty  = tid >> 4;
    const int tx  = tid & 15;
    const int b   = blockIdx.y >> 4;
    const int h   = blockIdx.y & 15;
    const int q0  = blockIdx.x * 128;
    const float nb = nbias[0];

    {
        int lr = tid >> 1;
        int d0 = (tid & 1) * 32;
        const float* src = rq + ((size_t)(b * Qn + q0 + lr) * Hn + h) * AD + d0;
        #pragma unroll
        for (int j = 0; j < 8; j++) {
            float4 v = *(const float4*)(src + j * 4);
            int d = d0 + j * 4;
            Qs[lr*65+d]=v.x; Qs[lr*65+d+1]=v.y; Qs[lr*65+d+2]=v.z; Qs[lr*65+d+3]=v.w;
        }
    }

    float oacc[8][4] = {};
    float rs[8] = {};
    const int* mrow = mask + (size_t)b * Qn * Sn + (size_t)q0 * Sn;

    for (int s0 = 0; s0 < Sn; s0 += 64) {
        __syncthreads();
        {
            int lr = tid >> 2;
            int d0 = (tid & 3) * 16;
            const float* kb = kvb + (size_t)(b * Sn + s0 + lr) * (2 * Dn) + h * AD + d0;
            #pragma unroll
            for (int j = 0; j < 4; j++) {
                int d = d0 + j * 4;
                float4 kk = *(const float4*)(kb + j * 4);
                Ks[lr*65+d]=kk.x; Ks[lr*65+d+1]=kk.y; Ks[lr*65+d+2]=kk.z; Ks[lr*65+d+3]=kk.w;
                float4 vv = *(const float4*)(kb + Dn + j * 4);
                Vs[lr*65+d]=vv.x; Vs[lr*65+d+1]=vv.y; Vs[lr*65+d+2]=vv.z; Vs[lr*65+d+3]=vv.w;
            }
        }
        __syncthreads();

        float sacc[8][4] = {};
        #pragma unroll 8
        for (int k = 0; k < AD; k++) {
            float ar[8], br[4];
            #pragma unroll
            for (int i = 0; i < 8; i++) ar[i] = Qs[(ty*8+i)*65 + k];
            #pragma unroll
            for (int j = 0; j < 4; j++) br[j] = Ks[(tx*4+j)*65 + k];
            #pragma unroll
            for (int i = 0; i < 8; i++)
                #pragma unroll
                for (int j = 0; j < 4; j++)
                    sacc[i][j] += ar[i] * br[j];
        }

        #pragma unroll
        for (int i = 0; i < 8; i++) {
            const int* mp = mrow + (size_t)(ty*8+i) * Sn + s0 + tx*4;
            int4 mv = *(const int4*)mp;
            #pragma unroll
            for (int j = 0; j < 4; j++) {
                int m = (j == 0) ? mv.x : (j == 1) ? mv.y : (j == 2) ? mv.z : mv.w;
                float t = sacc[i][j] * 0.125f + nb;
                t = m ? 0.0f : fmaxf(t, 0.0f);
                t = t * t;
                rs[i] += t;
                Ts[(ty*8+i)*65 + tx*4 + j] = t;
            }
        }
        __syncthreads();

        #pragma unroll 8
        for (int k = 0; k < 64; k++) {
            float tr[8], vr[4];
            #pragma unroll
            for (int i = 0; i < 8; i++) tr[i] = Ts[(ty*8+i)*65 + k];
            #pragma unroll
            for (int j = 0; j < 4; j++) vr[j] = Vs[k*65 + tx*4 + j];
            #pragma unroll
            for (int i = 0; i < 8; i++)
                #pragma unroll
                for (int j = 0; j < 4; j++)
                    oacc[i][j] += tr[i] * vr[j];
        }
    }

    __syncthreads();
    #pragma unroll
    for (int i = 0; i < 8; i++) Ks[(ty*8+i)*16 + tx] = rs[i];
    __syncthreads();
    if (tid < 128) {
        float d = 1e-32f;
        #pragma unroll
        for (int t = 0; t < 16; t++) d += Ks[tid*16 + t];
        Vs[tid] = d;
    }
    __syncthreads();

    #pragma unroll
    for (int i = 0; i < 8; i++) {
        float inv = 1.0f / Vs[ty*8 + i];
        float* op = o + ((size_t)(b * Qn + q0 + ty*8 + i) * Hn + h) * AD + tx*4;
        op[0] = oacc[i][0] * inv;
        op[1] = oacc[i][1] * inv;
        op[2] = oacc[i][2] * inv;
        op[3] = oacc[i][3] * inv;
    }
}

// ---------------------------------------------------------------------------
extern "C" void kernel_launch(void* const* d_in, const int* in_sizes, int n_in,
                              void* d_out, int out_size) {
    const float* iQ    = (const float*)d_in[0];
    const float* iK    = (const float*)d_in[1];
    const int*   mask  = (const int*)d_in[2];
    const float* Wq    = (const float*)d_in[3];
    const float* Wkv   = (const float*)d_in[4];
    const float* Wo    = (const float*)d_in[5];
    const float* nbias = (const float*)d_in[6];
    float* out = (float*)d_out;

    float *rq, *kvb, *ob;
    cudaGetSymbolAddress((void**)&rq,  g_rq);
    cudaGetSymbolAddress((void**)&kvb, g_kv);
    cudaGetSymbolAddress((void**)&ob,  g_o);
    __nv_bfloat16 *xqh,*xql,*xkh,*xkl,*obh,*obl,*wqh,*wql,*wkvh,*wkvl,*woh,*wol;
    cudaGetSymbolAddress((void**)&xqh, g_xq_h);  cudaGetSymbolAddress((void**)&xql, g_xq_l);
    cudaGetSymbolAddress((void**)&xkh, g_xk_h);  cudaGetSymbolAddress((void**)&xkl, g_xk_l);
    cudaGetSymbolAddress((void**)&obh, g_ob_h);  cudaGetSymbolAddress((void**)&obl, g_ob_l);
    cudaGetSymbolAddress((void**)&wqh, g_wq_h);  cudaGetSymbolAddress((void**)&wql, g_wq_l);
    cudaGetSymbolAddress((void**)&wkvh, g_wkv_h);cudaGetSymbolAddress((void**)&wkvl, g_wkv_l);
    cudaGetSymbolAddress((void**)&woh, g_wo_h);  cudaGetSymbolAddress((void**)&wol, g_wo_l);

    cudaFuncSetAttribute(gemm_mma_split, cudaFuncAttributeMaxDynamicSharedMemorySize, GEMM_SMEM);
    cudaFuncSetAttribute(attn_kernel, cudaFuncAttributeMaxDynamicSharedMemorySize, ATTN_SMEM);

    // 0) split fp32 -> bf16 hi/lo
    cvt_split<<<(MQ*Dn)/1024, 256>>>(iQ,  xqh, xql, MQ*Dn);
    cvt_split<<<(MS*Dn)/1024, 256>>>(iK,  xkh, xkl, MS*Dn);
    cvt_split<<<(Dn*Dn)/1024, 256>>>(Wq,  wqh, wql, Dn*Dn);
    cvt_split<<<(2*Dn*Dn)/1024, 256>>>(Wkv, wkvh, wkvl, 2*Dn*Dn);
    cvt_split<<<(Dn*Dn)/1024, 256>>>(Wo,  woh, wol, Dn*Dn);

    // 1) projections (warp-MMA split-bf16)
    gemm_mma_split<<<dim3(Dn/128,   MQ/128), 256, GEMM_SMEM>>>(xqh, xql, wqh,  wql,  rq,  MQ, Dn,   Dn);
    gemm_mma_split<<<dim3(2*Dn/128, MS/128), 256, GEMM_SMEM>>>(xkh, xkl, wkvh, wkvl, kvb, MS, 2*Dn, Dn);

    // 2) attention (fp32 SIMT, unchanged)
    attn_kernel<<<dim3(Qn/128, B_*Hn), 256, ATTN_SMEM>>>(rq, kvb, mask, nbias, ob);

    // 3) output projection
    cvt_split<<<(MQ*Dn)/1024, 256>>>(ob, obh, obl, MQ*Dn);
    gemm_mma_split<<<dim3(Dn/128, MQ/128), 256, GEMM_SMEM>>>(obh, obl, woh, wol, out, MQ, Dn, Dn);
}

// round 15
// speedup vs baseline: 2.2146x; 1.5821x over previous
#include <cuda_runtime.h>
#include <cuda_bf16.h>
#include <cstdint>

// Problem dims
#define B_  2
#define Qn  2048
#define Sn  2048
#define Dn  1024
#define Hn  16
#define AD  64
#define MQ  (B_ * Qn)   // 4096
#define MS  (B_ * Sn)   // 4096

// ---------------- scratch (__device__ globals; no allocs allowed) ----------
__device__ float g_o [(size_t)MQ * Dn];

__device__ __nv_bfloat16 g_xq_h[(size_t)MQ * Dn],  g_xq_l[(size_t)MQ * Dn];
__device__ __nv_bfloat16 g_xk_h[(size_t)MS * Dn],  g_xk_l[(size_t)MS * Dn];
__device__ __nv_bfloat16 g_ob_h[(size_t)MQ * Dn],  g_ob_l[(size_t)MQ * Dn];
__device__ __nv_bfloat16 g_wq_h[(size_t)Dn * Dn],  g_wq_l[(size_t)Dn * Dn];
__device__ __nv_bfloat16 g_wkv_h[(size_t)2 * Dn * Dn], g_wkv_l[(size_t)2 * Dn * Dn];
__device__ __nv_bfloat16 g_wo_h[(size_t)Dn * Dn],  g_wo_l[(size_t)Dn * Dn];
// projection outputs in split bf16 (consumed by attention)
__device__ __nv_bfloat16 g_rq_h[(size_t)MQ * Dn],  g_rq_l[(size_t)MQ * Dn];
__device__ __nv_bfloat16 g_kv_h[(size_t)MS * 2 * Dn], g_kv_l[(size_t)MS * 2 * Dn];

// ---------------- warp-MMA helpers (sm_80+ PTX, family-portable) -----------
__device__ __forceinline__ uint32_t smem_u32(const void* p) {
    uint32_t a;
    asm("{ .reg .u64 t; cvta.to.shared.u64 t, %1; cvt.u32.u64 %0, t; }" : "=r"(a) : "l"(p));
    return a;
}
__device__ __forceinline__ void ldsm_x4(uint32_t& r0, uint32_t& r1, uint32_t& r2,
                                        uint32_t& r3, uint32_t addr) {
    asm volatile("ldmatrix.sync.aligned.m8n8.x4.shared.b16 {%0,%1,%2,%3}, [%4];"
                 : "=r"(r0), "=r"(r1), "=r"(r2), "=r"(r3) : "r"(addr));
}
__device__ __forceinline__ void ldsm_x2(uint32_t& r0, uint32_t& r1, uint32_t addr) {
    asm volatile("ldmatrix.sync.aligned.m8n8.x2.shared.b16 {%0,%1}, [%2];"
                 : "=r"(r0), "=r"(r1) : "r"(addr));
}
__device__ __forceinline__ void ldsm_x2t(uint32_t& r0, uint32_t& r1, uint32_t addr) {
    asm volatile("ldmatrix.sync.aligned.m8n8.x2.trans.shared.b16 {%0,%1}, [%2];"
                 : "=r"(r0), "=r"(r1) : "r"(addr));
}
__device__ __forceinline__ void mma16816(float* d, const uint32_t* a, const uint32_t* b) {
    asm volatile("mma.sync.aligned.m16n8k16.row.col.f32.bf16.bf16.f32 "
                 "{%0,%1,%2,%3}, {%4,%5,%6,%7}, {%8,%9}, {%0,%1,%2,%3};"
                 : "+f"(d[0]), "+f"(d[1]), "+f"(d[2]), "+f"(d[3])
                 : "r"(a[0]), "r"(a[1]), "r"(a[2]), "r"(a[3]), "r"(b[0]), "r"(b[1]));
}
__device__ __forceinline__ uint32_t pack_bf2(float lo, float hi) {
    __nv_bfloat162 t(__float2bfloat16(lo), __float2bfloat16(hi));
    return *(uint32_t*)&t;
}

// ---------------------------------------------------------------------------
// fp32 -> (hi, lo) bf16 split:  x = hi + lo, lo = bf16(x - hi)
// ---------------------------------------------------------------------------
__global__ __launch_bounds__(256)
void cvt_split(const float* __restrict__ x, __nv_bfloat16* __restrict__ h,
               __nv_bfloat16* __restrict__ l, int n) {
    int i = (blockIdx.x * 256 + threadIdx.x) * 4;
    if (i >= n) return;
    float4 v = *(const float4*)(x + i);
    __nv_bfloat16 h0 = __float2bfloat16(v.x), h1 = __float2bfloat16(v.y);
    __nv_bfloat16 h2 = __float2bfloat16(v.z), h3 = __float2bfloat16(v.w);
    __nv_bfloat16 l0 = __float2bfloat16(v.x - __bfloat162float(h0));
    __nv_bfloat16 l1 = __float2bfloat16(v.y - __bfloat162float(h1));
    __nv_bfloat16 l2 = __float2bfloat16(v.z - __bfloat162float(h2));
    __nv_bfloat16 l3 = __float2bfloat16(v.w - __bfloat162float(h3));
    ((__nv_bfloat162*)(h + i))[0] = __nv_bfloat162(h0, h1);
    ((__nv_bfloat162*)(h + i))[1] = __nv_bfloat162(h2, h3);
    ((__nv_bfloat162*)(l + i))[0] = __nv_bfloat162(l0, l1);
    ((__nv_bfloat162*)(l + i))[1] = __nv_bfloat162(l2, l3);
}

// ---------------------------------------------------------------------------
// Split-bf16 warp-MMA GEMM:  Out[m,n] = sum_k A[m,k]*B[n,k]  (X @ W^T)
// D += Ah*Bh + Ah*Bl + Al*Bh (fp32 accum). CTA 128x128, K-chunk 64, 8 warps.
// Epilogue writes fp32 (Outf) and/or split-bf16 (Outh/Outl).
// ---------------------------------------------------------------------------
#define KC   64
#define LDS  72
#define TILE_B (128 * LDS * 2)          // 18432 B per tile
#define GEMM_SMEM (4 * TILE_B)          // 73728 B

__global__ __launch_bounds__(256)
void gemm_mma_split(const __nv_bfloat16* __restrict__ Ah, const __nv_bfloat16* __restrict__ Al,
                    const __nv_bfloat16* __restrict__ Bh, const __nv_bfloat16* __restrict__ Bl,
                    float* __restrict__ Outf,
                    __nv_bfloat16* __restrict__ Outh, __nv_bfloat16* __restrict__ Outl,
                    int M, int N, int K) {
    extern __shared__ char smc[];
    __nv_bfloat16* sAh = (__nv_bfloat16*)smc;
    __nv_bfloat16* sAl = sAh + 128 * LDS;
    __nv_bfloat16* sBh = sAl + 128 * LDS;
    __nv_bfloat16* sBl = sBh + 128 * LDS;

    const int tid  = threadIdx.x;
    const int lane = tid & 31;
    const int wid  = tid >> 5;
    const int wm   = wid >> 2;
    const int wn   = wid & 3;
    const int m0   = blockIdx.y * 128;
    const int n0   = blockIdx.x * 128;
    const uint32_t sb = smem_u32(smc);

    float acc[4][4][4] = {};

    const uint32_t aoff = ((uint32_t)((lane & 15) * LDS) + (lane >> 4) * 8) * 2;
    const uint32_t boff = ((uint32_t)((lane & 7) * LDS) + ((lane >> 3) & 1) * 8) * 2;

    for (int k0 = 0; k0 < K; k0 += KC) {
        #pragma unroll
        for (int i = 0; i < 4; i++) {
            const int linear = i * 256 + tid;
            const int row = linear >> 3;
            const int c   = (linear & 7) * 8;
            const size_t ga = (size_t)(m0 + row) * K + k0 + c;
            const size_t gb = (size_t)(n0 + row) * K + k0 + c;
            *(uint4*)(sAh + row * LDS + c) = *(const uint4*)(Ah + ga);
            *(uint4*)(sAl + row * LDS + c) = *(const uint4*)(Al + ga);
            *(uint4*)(sBh + row * LDS + c) = *(const uint4*)(Bh + gb);
            *(uint4*)(sBl + row * LDS + c) = *(const uint4*)(Bl + gb);
        }
        __syncthreads();

        #pragma unroll
        for (int ks = 0; ks < KC / 16; ks++) {
            const uint32_t kso = (uint32_t)(ks * 16 * 2);
            uint32_t ah[4][4], al[4][4], bh[4][2], bl[4][2];
            #pragma unroll
            for (int mt = 0; mt < 4; mt++) {
                const uint32_t o = (uint32_t)((wm * 64 + mt * 16) * LDS * 2) + aoff + kso;
                ldsm_x4(ah[mt][0], ah[mt][1], ah[mt][2], ah[mt][3], sb + o);
                ldsm_x4(al[mt][0], al[mt][1], al[mt][2], al[mt][3], sb + TILE_B + o);
            }
            #pragma unroll
            for (int nt = 0; nt < 4; nt++) {
                const uint32_t o = (uint32_t)((wn * 32 + nt * 8) * LDS * 2) + boff + kso;
                ldsm_x2(bh[nt][0], bh[nt][1], sb + 2 * TILE_B + o);
                ldsm_x2(bl[nt][0], bl[nt][1], sb + 3 * TILE_B + o);
            }
            #pragma unroll
            for (int mt = 0; mt < 4; mt++)
                #pragma unroll
                for (int nt = 0; nt < 4; nt++) {
                    mma16816(acc[mt][nt], ah[mt], bh[nt]);
                    mma16816(acc[mt][nt], ah[mt], bl[nt]);
                    mma16816(acc[mt][nt], al[mt], bh[nt]);
                }
        }
        __syncthreads();
    }

    #pragma unroll
    for (int mt = 0; mt < 4; mt++) {
        const int mA = m0 + wm * 64 + mt * 16 + (lane >> 2);
        #pragma unroll
        for (int nt = 0; nt < 4; nt++) {
            const int n = n0 + wn * 32 + nt * 8 + (lane & 3) * 2;
            #pragma unroll
            for (int half = 0; half < 2; half++) {
                const size_t idx = (size_t)(mA + half * 8) * N + n;
                const float v0 = acc[mt][nt][half * 2], v1 = acc[mt][nt][half * 2 + 1];
                if (Outf) *(float2*)(Outf + idx) = make_float2(v0, v1);
                if (Outh) {
                    __nv_bfloat16 h0 = __float2bfloat16(v0), h1 = __float2bfloat16(v1);
                    *(uint32_t*)(Outh + idx) = pack_bf2(v0, v1);
                    __nv_bfloat162 lo(__float2bfloat16(v0 - __bfloat162float(h0)),
                                      __float2bfloat16(v1 - __bfloat162float(h1)));
                    *(uint32_t*)(Outl + idx) = *(uint32_t*)&lo;
                }
            }
        }
    }
}

// ---------------------------------------------------------------------------
// Tensor-core fused attention. Block = 128 q-rows x 1 head, 8 warps.
// Warp owns 16 q-rows. S-tiles of 64.
// Scores: split-bf16 QK^T (3 MMAs).
// P ALSO split hi/lo (R14 fix: bf16 P rounding alone cost 1.4e-3):
//   AV = Ph@Vh + Ph@Vl + Pl@Vh (3 MMAs); denominator from exact fp32 t.
// ---------------------------------------------------------------------------
// smem (bf16 units, LDS=72 stride): Qh[128], Ql[128], Kh[64], Kl[64], Vh[64], Vl[64]
#define AQH 0
#define AQL (128 * LDS)
#define AKH (256 * LDS)
#define AKL (320 * LDS)
#define AVH (384 * LDS)
#define AVL (448 * LDS)
#define ATTN_SMEM (512 * LDS * 2)   // 73728 B

__global__ __launch_bounds__(256)
void attn_mma(const __nv_bfloat16* __restrict__ qh_g, const __nv_bfloat16* __restrict__ ql_g,
              const __nv_bfloat16* __restrict__ kvh_g, const __nv_bfloat16* __restrict__ kvl_g,
              const int* __restrict__ mask, const float* __restrict__ nbias,
              float* __restrict__ o) {
    extern __shared__ char smc[];
    __nv_bfloat16* sm = (__nv_bfloat16*)smc;
    const uint32_t sb = smem_u32(smc);

    const int tid  = threadIdx.x;
    const int lane = tid & 31;
    const int wid  = tid >> 5;
    const int b    = blockIdx.y >> 4;
    const int h    = blockIdx.y & 15;
    const int q0   = blockIdx.x * 128;
    const float nb = nbias[0];

    // ---- load Q tile (128 x 64, hi+lo) ----
    #pragma unroll
    for (int i = 0; i < 4; i++) {
        const int linear = i * 256 + tid;
        const int row = linear >> 3;          // 0..127
        const int c   = (linear & 7) * 8;     // 0..56
        const size_t g = (size_t)(b * Qn + q0 + row) * Dn + h * AD + c;
        *(uint4*)(sm + AQH + row * LDS + c) = *(const uint4*)(qh_g + g);
        *(uint4*)(sm + AQL + row * LDS + c) = *(const uint4*)(ql_g + g);
    }
    __syncthreads();

    // ---- preload Q fragments (row strip wid*16, all 4 k-steps) ----
    const uint32_t aoff = ((uint32_t)((lane & 15) * LDS) + (lane >> 4) * 8) * 2;
    uint32_t qh[4][4], ql[4][4];
    #pragma unroll
    for (int ks = 0; ks < 4; ks++) {
        const uint32_t off = (uint32_t)(wid * 16 * LDS * 2) + aoff + (uint32_t)(ks * 32);
        ldsm_x4(qh[ks][0], qh[ks][1], qh[ks][2], qh[ks][3], sb + AQH * 2 + off);
        ldsm_x4(ql[ks][0], ql[ks][1], ql[ks][2], ql[ks][3], sb + AQL * 2 + off);
    }

    const uint32_t boff = ((uint32_t)((lane & 7) * LDS) + ((lane >> 3) & 1) * 8) * 2;
    const int r0 = wid * 16 + (lane >> 2);          // local q row (and +8)
    const int* mrow = mask + (size_t)b * Qn * Sn + (size_t)(q0 + r0) * Sn + (lane & 3) * 2;

    float oacc[8][4] = {};
    float rs0 = 0.0f, rs1 = 0.0f;

    for (int s0 = 0; s0 < Sn; s0 += 64) {
        __syncthreads();
        // ---- load K (hi+lo) and V (hi+lo) tiles (64 x 64) ----
        #pragma unroll
        for (int i = 0; i < 2; i++) {
            const int linear = i * 256 + tid;
            const int row = linear >> 3;
            const int c   = (linear & 7) * 8;
            const size_t gk = (size_t)(b * Sn + s0 + row) * (2 * Dn) + h * AD + c;
            *(uint4*)(sm + AKH + row * LDS + c) = *(const uint4*)(kvh_g + gk);
            *(uint4*)(sm + AKL + row * LDS + c) = *(const uint4*)(kvl_g + gk);
            *(uint4*)(sm + AVH + row * LDS + c) = *(const uint4*)(kvh_g + gk + Dn);
            *(uint4*)(sm + AVL + row * LDS + c) = *(const uint4*)(kvl_g + gk + Dn);
        }
        __syncthreads();

        // ---- scores: 16 x 64 per warp, split-bf16 (3 MMAs) ----
        float sacc[8][4] = {};
        #pragma unroll
        for (int ks = 0; ks < 4; ks++) {
            #pragma unroll
            for (int nt = 0; nt < 8; nt++) {
                uint32_t kh[2], kl[2];
                const uint32_t off = (uint32_t)(nt * 8 * LDS * 2) + boff + (uint32_t)(ks * 32);
                ldsm_x2(kh[0], kh[1], sb + AKH * 2 + off);
                ldsm_x2(kl[0], kl[1], sb + AKL * 2 + off);
                mma16816(sacc[nt], qh[ks], kh);
                mma16816(sacc[nt], qh[ks], kl);
                mma16816(sacc[nt], ql[ks], kh);
            }
        }

        // ---- epilogue: mask + relu^2, split-bf16 repack of P ----
        uint32_t afh[4][4], afl[4][4];
        #pragma unroll
        for (int nt = 0; nt < 8; nt++) {
            const int col = s0 + nt * 8;
            const int2 m0v = *(const int2*)(mrow + col);
            const int2 m1v = *(const int2*)(mrow + 8 * Sn + col);
            float t0 = m0v.x ? 0.0f : fmaxf(fmaf(sacc[nt][0], 0.125f, nb), 0.0f);
            float t1 = m0v.y ? 0.0f : fmaxf(fmaf(sacc[nt][1], 0.125f, nb), 0.0f);
            float t2 = m1v.x ? 0.0f : fmaxf(fmaf(sacc[nt][2], 0.125f, nb), 0.0f);
            float t3 = m1v.y ? 0.0f : fmaxf(fmaf(sacc[nt][3], 0.125f, nb), 0.0f);
            t0 *= t0; t1 *= t1; t2 *= t2; t3 *= t3;
            // exact fp32 denominator
            rs0 += t0 + t1;
            rs1 += t2 + t3;
            // split P: ph + pl ~ t to ~2^-18 relative
            __nv_bfloat16 h0 = __float2bfloat16(t0), h1 = __float2bfloat16(t1);
            __nv_bfloat16 h2 = __float2bfloat16(t2), h3 = __float2bfloat16(t3);
            __nv_bfloat16 e0 = __float2bfloat16(t0 - __bfloat162float(h0));
            __nv_bfloat16 e1 = __float2bfloat16(t1 - __bfloat162float(h1));
            __nv_bfloat16 e2 = __float2bfloat16(t2 - __bfloat162float(h2));
            __nv_bfloat16 e3 = __float2bfloat16(t3 - __bfloat162float(h3));
            __nv_bfloat162 ph01(h0, h1), ph23(h2, h3), pl01(e0, e1), pl23(e2, e3);
            afh[nt >> 1][(nt & 1) ? 2 : 0] = *(uint32_t*)&ph01;
            afh[nt >> 1][(nt & 1) ? 3 : 1] = *(uint32_t*)&ph23;
            afl[nt >> 1][(nt & 1) ? 2 : 0] = *(uint32_t*)&pl01;
            afl[nt >> 1][(nt & 1) ? 3 : 1] = *(uint32_t*)&pl23;
        }

        // ---- AV: o += Ph@Vh + Ph@Vl + Pl@Vh ----
        #pragma unroll
        for (int ks = 0; ks < 4; ks++) {
            #pragma unroll
            for (int dt = 0; dt < 8; dt++) {
                uint32_t vh[2], vl[2];
                const uint32_t off = (uint32_t)((ks * 16 + (lane & 15)) * LDS * 2)
                                   + (uint32_t)(dt * 16);
                ldsm_x2t(vh[0], vh[1], sb + AVH * 2 + off);
                ldsm_x2t(vl[0], vl[1], sb + AVL * 2 + off);
                mma16816(oacc[dt], afh[ks], vh);
                mma16816(oacc[dt], afh[ks], vl);
                mma16816(oacc[dt], afl[ks], vh);
            }
        }
    }

    // ---- normalize and store ----
    rs0 += __shfl_xor_sync(0xFFFFFFFF, rs0, 1);
    rs0 += __shfl_xor_sync(0xFFFFFFFF, rs0, 2);
    rs1 += __shfl_xor_sync(0xFFFFFFFF, rs1, 1);
    rs1 += __shfl_xor_sync(0xFFFFFFFF, rs1, 2);
    const float inv0 = 1.0f / (rs0 + 1e-32f);
    const float inv1 = 1.0f / (rs1 + 1e-32f);

    const size_t ob0 = (size_t)(b * Qn + q0 + r0) * Dn + h * AD + (lane & 3) * 2;
    const size_t ob1 = ob0 + (size_t)8 * Dn;
    #pragma unroll
    for (int dt = 0; dt < 8; dt++) {
        *(float2*)(o + ob0 + dt * 8) = make_float2(oacc[dt][0] * inv0, oacc[dt][1] * inv0);
        *(float2*)(o + ob1 + dt * 8) = make_float2(oacc[dt][2] * inv1, oacc[dt][3] * inv1);
    }
}

// ---------------------------------------------------------------------------
extern "C" void kernel_launch(void* const* d_in, const int* in_sizes, int n_in,
                              void* d_out, int out_size) {
    const float* iQ    = (const float*)d_in[0];
    const float* iK    = (const float*)d_in[1];
    const int*   mask  = (const int*)d_in[2];
    const float* Wq    = (const float*)d_in[3];
    const float* Wkv   = (const float*)d_in[4];
    const float* Wo    = (const float*)d_in[5];
    const float* nbias = (const float*)d_in[6];
    float* out = (float*)d_out;

    float* ob;
    cudaGetSymbolAddress((void**)&ob, g_o);
    __nv_bfloat16 *xqh,*xql,*xkh,*xkl,*obh,*obl,*wqh,*wql,*wkvh,*wkvl,*woh,*wol;
    __nv_bfloat16 *rqh,*rql,*kvh,*kvl;
    cudaGetSymbolAddress((void**)&xqh, g_xq_h);  cudaGetSymbolAddress((void**)&xql, g_xq_l);
    cudaGetSymbolAddress((void**)&xkh, g_xk_h);  cudaGetSymbolAddress((void**)&xkl, g_xk_l);
    cudaGetSymbolAddress((void**)&obh, g_ob_h);  cudaGetSymbolAddress((void**)&obl, g_ob_l);
    cudaGetSymbolAddress((void**)&wqh, g_wq_h);  cudaGetSymbolAddress((void**)&wql, g_wq_l);
    cudaGetSymbolAddress((void**)&wkvh, g_wkv_h);cudaGetSymbolAddress((void**)&wkvl, g_wkv_l);
    cudaGetSymbolAddress((void**)&woh, g_wo_h);  cudaGetSymbolAddress((void**)&wol, g_wo_l);
    cudaGetSymbolAddress((void**)&rqh, g_rq_h);  cudaGetSymbolAddress((void**)&rql, g_rq_l);
    cudaGetSymbolAddress((void**)&kvh, g_kv_h);  cudaGetSymbolAddress((void**)&kvl, g_kv_l);

    cudaFuncSetAttribute(gemm_mma_split, cudaFuncAttributeMaxDynamicSharedMemorySize, GEMM_SMEM);
    cudaFuncSetAttribute(attn_mma, cudaFuncAttributeMaxDynamicSharedMemorySize, ATTN_SMEM);

    // 0) split fp32 -> bf16 hi/lo (inputs + weights)
    cvt_split<<<(MQ*Dn)/1024, 256>>>(iQ,  xqh, xql, MQ*Dn);
    cvt_split<<<(MS*Dn)/1024, 256>>>(iK,  xkh, xkl, MS*Dn);
    cvt_split<<<(Dn*Dn)/1024, 256>>>(Wq,  wqh, wql, Dn*Dn);
    cvt_split<<<(2*Dn*Dn)/1024, 256>>>(Wkv, wkvh, wkvl, 2*Dn*Dn);
    cvt_split<<<(Dn*Dn)/1024, 256>>>(Wo,  woh, wol, Dn*Dn);

    // 1) projections -> split bf16 outputs (no fp32 intermediate)
    gemm_mma_split<<<dim3(Dn/128,   MQ/128), 256, GEMM_SMEM>>>(xqh, xql, wqh,  wql,
                                                               nullptr, rqh, rql, MQ, Dn,   Dn);
    gemm_mma_split<<<dim3(2*Dn/128, MS/128), 256, GEMM_SMEM>>>(xkh, xkl, wkvh, wkvl,
                                                               nullptr, kvh, kvl, MS, 2*Dn, Dn);

    // 2) attention (tensor-core, fused)
    attn_mma<<<dim3(Qn/128, B_*Hn), 256, ATTN_SMEM>>>(rqh, rql, kvh, kvl, mask, nbias, ob);

    // 3) output projection (fp32 out)
    cvt_split<<<(MQ*Dn)/1024, 256>>>(ob, obh, obl, MQ*Dn);
    gemm_mma_split<<<dim3(Dn/128, MQ/128), 256, GEMM_SMEM>>>(obh, obl, woh, wol,
                                                             out, nullptr, nullptr, MQ, Dn, Dn);
}

// round 17
// speedup vs baseline: 2.4622x; 1.1118x over previous
#include <cuda_runtime.h>
#include <cuda_bf16.h>
#include <cstdint>

// Problem dims
#define B_  2
#define Qn  2048
#define Sn  2048
#define Dn  1024
#define Hn  16
#define AD  64
#define MQ  (B_ * Qn)   // 4096
#define MS  (B_ * Sn)   // 4096

// ---------------- scratch (__device__ globals; no allocs allowed) ----------
__device__ __nv_bfloat16 g_xq_h[(size_t)MQ * Dn],  g_xq_l[(size_t)MQ * Dn];
__device__ __nv_bfloat16 g_xk_h[(size_t)MS * Dn],  g_xk_l[(size_t)MS * Dn];
__device__ __nv_bfloat16 g_ob_h[(size_t)MQ * Dn],  g_ob_l[(size_t)MQ * Dn];
__device__ __nv_bfloat16 g_wq_h[(size_t)Dn * Dn],  g_wq_l[(size_t)Dn * Dn];
__device__ __nv_bfloat16 g_wkv_h[(size_t)2 * Dn * Dn], g_wkv_l[(size_t)2 * Dn * Dn];
__device__ __nv_bfloat16 g_wo_h[(size_t)Dn * Dn],  g_wo_l[(size_t)Dn * Dn];
// projection outputs in split bf16 (consumed by attention)
__device__ __nv_bfloat16 g_rq_h[(size_t)MQ * Dn],  g_rq_l[(size_t)MQ * Dn];
__device__ __nv_bfloat16 g_kv_h[(size_t)MS * 2 * Dn], g_kv_l[(size_t)MS * 2 * Dn];

// ---------------- warp-MMA helpers (sm_80+ PTX, family-portable) -----------
__device__ __forceinline__ uint32_t smem_u32(const void* p) {
    uint32_t a;
    asm("{ .reg .u64 t; cvta.to.shared.u64 t, %1; cvt.u32.u64 %0, t; }" : "=r"(a) : "l"(p));
    return a;
}
__device__ __forceinline__ void ldsm_x4(uint32_t& r0, uint32_t& r1, uint32_t& r2,
                                        uint32_t& r3, uint32_t addr) {
    asm volatile("ldmatrix.sync.aligned.m8n8.x4.shared.b16 {%0,%1,%2,%3}, [%4];"
                 : "=r"(r0), "=r"(r1), "=r"(r2), "=r"(r3) : "r"(addr));
}
__device__ __forceinline__ void ldsm_x4t(uint32_t& r0, uint32_t& r1, uint32_t& r2,
                                         uint32_t& r3, uint32_t addr) {
    asm volatile("ldmatrix.sync.aligned.m8n8.x4.trans.shared.b16 {%0,%1,%2,%3}, [%4];"
                 : "=r"(r0), "=r"(r1), "=r"(r2), "=r"(r3) : "r"(addr));
}
__device__ __forceinline__ void mma16816(float* d, const uint32_t* a, const uint32_t* b) {
    asm volatile("mma.sync.aligned.m16n8k16.row.col.f32.bf16.bf16.f32 "
                 "{%0,%1,%2,%3}, {%4,%5,%6,%7}, {%8,%9}, {%0,%1,%2,%3};"
                 : "+f"(d[0]), "+f"(d[1]), "+f"(d[2]), "+f"(d[3])
                 : "r"(a[0]), "r"(a[1]), "r"(a[2]), "r"(a[3]), "r"(b[0]), "r"(b[1]));
}
__device__ __forceinline__ uint32_t pack_bf2(float lo, float hi) {
    __nv_bfloat162 t(__float2bfloat16(lo), __float2bfloat16(hi));
    return *(uint32_t*)&t;
}
__device__ __forceinline__ void cpa16(uint32_t s, const void* g) {
    asm volatile("cp.async.cg.shared.global [%0], [%1], 16;" :: "r"(s), "l"(g));
}
#define CP_COMMIT() asm volatile("cp.async.commit_group;" ::: "memory")
#define CP_WAIT0()  asm volatile("cp.async.wait_group 0;"  ::: "memory")

// ---------------------------------------------------------------------------
// fp32 -> (hi, lo) bf16 split:  x = hi + lo, lo = bf16(x - hi)
// ---------------------------------------------------------------------------
__global__ __launch_bounds__(256)
void cvt_split(const float* __restrict__ x, __nv_bfloat16* __restrict__ h,
               __nv_bfloat16* __restrict__ l, int n) {
    int i = (blockIdx.x * 256 + threadIdx.x) * 4;
    if (i >= n) return;
    float4 v = *(const float4*)(x + i);
    __nv_bfloat16 h0 = __float2bfloat16(v.x), h1 = __float2bfloat16(v.y);
    __nv_bfloat16 h2 = __float2bfloat16(v.z), h3 = __float2bfloat16(v.w);
    __nv_bfloat16 l0 = __float2bfloat16(v.x - __bfloat162float(h0));
    __nv_bfloat16 l1 = __float2bfloat16(v.y - __bfloat162float(h1));
    __nv_bfloat16 l2 = __float2bfloat16(v.z - __bfloat162float(h2));
    __nv_bfloat16 l3 = __float2bfloat16(v.w - __bfloat162float(h3));
    ((__nv_bfloat162*)(h + i))[0] = __nv_bfloat162(h0, h1);
    ((__nv_bfloat162*)(h + i))[1] = __nv_bfloat162(h2, h3);
    ((__nv_bfloat162*)(l + i))[0] = __nv_bfloat162(l0, l1);
    ((__nv_bfloat162*)(l + i))[1] = __nv_bfloat162(l2, l3);
}

// ---------------------------------------------------------------------------
// Split-bf16 warp-MMA GEMM:  Out[m,n] = sum_k A[m,k]*B[n,k]  (X @ W^T)
// D += Ah*Bh + Ah*Bl + Al*Bh (fp32 accum). CTA 128x128, K-chunk 64, 8 warps.
// B-operand fragments via ldmatrix.x4 (one load feeds two n-tiles).
// ---------------------------------------------------------------------------
#define KC   64
#define LDS  72
#define TILE_B (128 * LDS * 2)          // 18432 B per tile
#define GEMM_SMEM (4 * TILE_B)          // 73728 B

__global__ __launch_bounds__(256)
void gemm_mma_split(const __nv_bfloat16* __restrict__ Ah, const __nv_bfloat16* __restrict__ Al,
                    const __nv_bfloat16* __restrict__ Bh, const __nv_bfloat16* __restrict__ Bl,
                    float* __restrict__ Outf,
                    __nv_bfloat16* __restrict__ Outh, __nv_bfloat16* __restrict__ Outl,
                    int M, int N, int K) {
    extern __shared__ char smc[];
    __nv_bfloat16* sAh = (__nv_bfloat16*)smc;
    __nv_bfloat16* sAl = sAh + 128 * LDS;
    __nv_bfloat16* sBh = sAl + 128 * LDS;
    __nv_bfloat16* sBl = sBh + 128 * LDS;

    const int tid  = threadIdx.x;
    const int lane = tid & 31;
    const int wid  = tid >> 5;
    const int wm   = wid >> 2;
    const int wn   = wid & 3;
    const int m0   = blockIdx.y * 128;
    const int n0   = blockIdx.x * 128;
    const uint32_t sb = smem_u32(smc);

    float acc[4][4][4] = {};

    const uint32_t aoff = ((uint32_t)((lane & 15) * LDS) + (lane >> 4) * 8) * 2;

    for (int k0 = 0; k0 < K; k0 += KC) {
        #pragma unroll
        for (int i = 0; i < 4; i++) {
            const int linear = i * 256 + tid;
            const int row = linear >> 3;
            const int c   = (linear & 7) * 8;
            const size_t ga = (size_t)(m0 + row) * K + k0 + c;
            const size_t gb = (size_t)(n0 + row) * K + k0 + c;
            *(uint4*)(sAh + row * LDS + c) = *(const uint4*)(Ah + ga);
            *(uint4*)(sAl + row * LDS + c) = *(const uint4*)(Al + ga);
            *(uint4*)(sBh + row * LDS + c) = *(const uint4*)(Bh + gb);
            *(uint4*)(sBl + row * LDS + c) = *(const uint4*)(Bl + gb);
        }
        __syncthreads();

        #pragma unroll
        for (int ks = 0; ks < KC / 16; ks++) {
            const uint32_t kso = (uint32_t)(ks * 16 * 2);
            uint32_t ah[4][4], al[4][4], bh[4][2], bl[4][2];
            #pragma unroll
            for (int mt = 0; mt < 4; mt++) {
                const uint32_t o = (uint32_t)((wm * 64 + mt * 16) * LDS * 2) + aoff + kso;
                ldsm_x4(ah[mt][0], ah[mt][1], ah[mt][2], ah[mt][3], sb + o);
                ldsm_x4(al[mt][0], al[mt][1], al[mt][2], al[mt][3], sb + TILE_B + o);
            }
            #pragma unroll
            for (int nt2 = 0; nt2 < 2; nt2++) {
                uint32_t h4[4], l4[4];
                const uint32_t o = (uint32_t)((wn * 32 + nt2 * 16) * LDS * 2) + aoff + kso;
                ldsm_x4(h4[0], h4[1], h4[2], h4[3], sb + 2 * TILE_B + o);
                ldsm_x4(l4[0], l4[1], l4[2], l4[3], sb + 3 * TILE_B + o);
                bh[2*nt2][0] = h4[0]; bh[2*nt2][1] = h4[2];
                bh[2*nt2+1][0] = h4[1]; bh[2*nt2+1][1] = h4[3];
                bl[2*nt2][0] = l4[0]; bl[2*nt2][1] = l4[2];
                bl[2*nt2+1][0] = l4[1]; bl[2*nt2+1][1] = l4[3];
            }
            #pragma unroll
            for (int mt = 0; mt < 4; mt++)
                #pragma unroll
                for (int nt = 0; nt < 4; nt++) {
                    mma16816(acc[mt][nt], ah[mt], bh[nt]);
                    mma16816(acc[mt][nt], ah[mt], bl[nt]);
                    mma16816(acc[mt][nt], al[mt], bh[nt]);
                }
        }
        __syncthreads();
    }

    #pragma unroll
    for (int mt = 0; mt < 4; mt++) {
        const int mA = m0 + wm * 64 + mt * 16 + (lane >> 2);
        #pragma unroll
        for (int nt = 0; nt < 4; nt++) {
            const int n = n0 + wn * 32 + nt * 8 + (lane & 3) * 2;
            #pragma unroll
            for (int half = 0; half < 2; half++) {
                const size_t idx = (size_t)(mA + half * 8) * N + n;
                const float v0 = acc[mt][nt][half * 2], v1 = acc[mt][nt][half * 2 + 1];
                if (Outf) *(float2*)(Outf + idx) = make_float2(v0, v1);
                if (Outh) {
                    __nv_bfloat16 h0 = __float2bfloat16(v0), h1 = __float2bfloat16(v1);
                    *(uint32_t*)(Outh + idx) = pack_bf2(v0, v1);
                    __nv_bfloat162 lo(__float2bfloat16(v0 - __bfloat162float(h0)),
                                      __float2bfloat16(v1 - __bfloat162float(h1)));
                    *(uint32_t*)(Outl + idx) = *(uint32_t*)&lo;
                }
            }
        }
    }
}

// ---------------------------------------------------------------------------
// Tensor-core fused attention. Block = 128 q-rows x 1 head, 8 warps.
// Warp owns 16 q-rows. S-tiles of 64, cp.async double-buffered K/V.
// Scores: split-bf16 QK^T (3 MMAs). P split hi/lo; AV = Ph@Vh+Ph@Vl+Pl@Vh.
// Mask prefetched ahead of score MMAs. Output written as split bf16.
// ---------------------------------------------------------------------------
// smem (bf16 units, LDS=72): Qh[128](9216), Ql[128](9216), 2 bufs x 4x64-row tiles
#define AQH   0
#define AQL   9216
#define ABUF0 18432
#define ABUF1 36864
#define TK    4608                       // 64 * LDS
#define ATTN_SMEM (55296 * 2)            // 110592 B

__device__ __forceinline__ void kv_async_load(uint32_t sb, uint32_t bufb,
        const __nv_bfloat16* kvh_g, const __nv_bfloat16* kvl_g,
        int b, int h, int s0, int tid) {
    #pragma unroll
    for (int i = 0; i < 2; i++) {
        const int linear = i * 256 + tid;
        const int row = linear >> 3;
        const int c   = (linear & 7) * 8;
        const size_t gk = (size_t)(b * Sn + s0 + row) * (2 * Dn) + h * AD + c;
        const uint32_t so = sb + (bufb + (uint32_t)(row * LDS + c)) * 2;
        cpa16(so,              kvh_g + gk);        // Kh
        cpa16(so + TK * 2,     kvl_g + gk);        // Kl
        cpa16(so + 2 * TK * 2, kvh_g + gk + Dn);   // Vh
        cpa16(so + 3 * TK * 2, kvl_g + gk + Dn);   // Vl
    }
}

__global__ __launch_bounds__(256)
void attn_mma(const __nv_bfloat16* __restrict__ qh_g, const __nv_bfloat16* __restrict__ ql_g,
              const __nv_bfloat16* __restrict__ kvh_g, const __nv_bfloat16* __restrict__ kvl_g,
              const int* __restrict__ mask, const float* __restrict__ nbias,
              __nv_bfloat16* __restrict__ obh, __nv_bfloat16* __restrict__ obl) {
    extern __shared__ char smc[];
    __nv_bfloat16* sm = (__nv_bfloat16*)smc;
    const uint32_t sb = smem_u32(smc);

    const int tid  = threadIdx.x;
    const int lane = tid & 31;
    const int wid  = tid >> 5;
    const int b    = blockIdx.y >> 4;
    const int h    = blockIdx.y & 15;
    const int q0   = blockIdx.x * 128;
    const float nb = nbias[0];

    // ---- load Q tile (128 x 64, hi+lo) ----
    #pragma unroll
    for (int i = 0; i < 4; i++) {
        const int linear = i * 256 + tid;
        const int row = linear >> 3;
        const int c   = (linear & 7) * 8;
        const size_t g = (size_t)(b * Qn + q0 + row) * Dn + h * AD + c;
        *(uint4*)(sm + AQH + row * LDS + c) = *(const uint4*)(qh_g + g);
        *(uint4*)(sm + AQL + row * LDS + c) = *(const uint4*)(ql_g + g);
    }
    // prefetch first K/V tile while Q settles
    kv_async_load(sb, ABUF0, kvh_g, kvl_g, b, h, 0, tid);
    CP_COMMIT();
    __syncthreads();

    // ---- preload Q fragments ----
    const uint32_t aoff = ((uint32_t)((lane & 15) * LDS) + (lane >> 4) * 8) * 2;
    uint32_t qh[4][4], ql[4][4];
    #pragma unroll
    for (int ks = 0; ks < 4; ks++) {
        const uint32_t off = (uint32_t)(wid * 16 * LDS * 2) + aoff + (uint32_t)(ks * 32);
        ldsm_x4(qh[ks][0], qh[ks][1], qh[ks][2], qh[ks][3], sb + AQH * 2 + off);
        ldsm_x4(ql[ks][0], ql[ks][1], ql[ks][2], ql[ks][3], sb + AQL * 2 + off);
    }

    const int r0 = wid * 16 + (lane >> 2);
    const int* mrow = mask + (size_t)b * Qn * Sn + (size_t)(q0 + r0) * Sn + (lane & 3) * 2;

    float oacc[8][4] = {};
    float rs0 = 0.0f, rs1 = 0.0f;

    for (int it = 0; it < Sn / 64; it++) {
        const int s0 = it * 64;
        CP_WAIT0();
        __syncthreads();
        if (it + 1 < Sn / 64) {
            kv_async_load(sb, (it & 1) ? ABUF0 : ABUF1, kvh_g, kvl_g, b, h, s0 + 64, tid);
            CP_COMMIT();
        }
        const uint32_t bufb = (it & 1) ? ABUF1 : ABUF0;
        const uint32_t sbKH = sb + bufb * 2;
        const uint32_t sbKL = sbKH + TK * 2;
        const uint32_t sbVH = sbKH + 2 * TK * 2;
        const uint32_t sbVL = sbKH + 3 * TK * 2;

        // ---- mask prefetch (overlaps with score MMAs) ----
        int2 mv0[8], mv1[8];
        #pragma unroll
        for (int nt = 0; nt < 8; nt++) {
            const int col = s0 + nt * 8;
            mv0[nt] = *(const int2*)(mrow + col);
            mv1[nt] = *(const int2*)(mrow + 8 * Sn + col);
        }

        // ---- scores: 16 x 64 per warp, split-bf16 (3 MMAs), x4 K loads ----
        float sacc[8][4] = {};
        #pragma unroll
        for (int ks = 0; ks < 4; ks++) {
            #pragma unroll
            for (int nt2 = 0; nt2 < 4; nt2++) {
                uint32_t h4[4], l4[4];
                const uint32_t off = (uint32_t)(nt2 * 16 * LDS * 2) + aoff + (uint32_t)(ks * 32);
                ldsm_x4(h4[0], h4[1], h4[2], h4[3], sbKH + off);
                ldsm_x4(l4[0], l4[1], l4[2], l4[3], sbKL + off);
                uint32_t bh0[2] = {h4[0], h4[2]}, bh1[2] = {h4[1], h4[3]};
                uint32_t bl0[2] = {l4[0], l4[2]}, bl1[2] = {l4[1], l4[3]};
                mma16816(sacc[2*nt2],   qh[ks], bh0);
                mma16816(sacc[2*nt2],   qh[ks], bl0);
                mma16816(sacc[2*nt2],   ql[ks], bh0);
                mma16816(sacc[2*nt2+1], qh[ks], bh1);
                mma16816(sacc[2*nt2+1], qh[ks], bl1);
                mma16816(sacc[2*nt2+1], ql[ks], bh1);
            }
        }

        // ---- epilogue: mask + relu^2, split-bf16 repack of P ----
        uint32_t afh[4][4], afl[4][4];
        #pragma unroll
        for (int nt = 0; nt < 8; nt++) {
            float t0 = mv0[nt].x ? 0.0f : fmaxf(fmaf(sacc[nt][0], 0.125f, nb), 0.0f);
            float t1 = mv0[nt].y ? 0.0f : fmaxf(fmaf(sacc[nt][1], 0.125f, nb), 0.0f);
            float t2 = mv1[nt].x ? 0.0f : fmaxf(fmaf(sacc[nt][2], 0.125f, nb), 0.0f);
            float t3 = mv1[nt].y ? 0.0f : fmaxf(fmaf(sacc[nt][3], 0.125f, nb), 0.0f);
            t0 *= t0; t1 *= t1; t2 *= t2; t3 *= t3;
            rs0 += t0 + t1;
            rs1 += t2 + t3;
            __nv_bfloat16 h0 = __float2bfloat16(t0), h1 = __float2bfloat16(t1);
            __nv_bfloat16 h2 = __float2bfloat16(t2), h3 = __float2bfloat16(t3);
            __nv_bfloat16 e0 = __float2bfloat16(t0 - __bfloat162float(h0));
            __nv_bfloat16 e1 = __float2bfloat16(t1 - __bfloat162float(h1));
            __nv_bfloat16 e2 = __float2bfloat16(t2 - __bfloat162float(h2));
            __nv_bfloat16 e3 = __float2bfloat16(t3 - __bfloat162float(h3));
            __nv_bfloat162 ph01(h0, h1), ph23(h2, h3), pl01(e0, e1), pl23(e2, e3);
            afh[nt >> 1][(nt & 1) ? 2 : 0] = *(uint32_t*)&ph01;
            afh[nt >> 1][(nt & 1) ? 3 : 1] = *(uint32_t*)&ph23;
            afl[nt >> 1][(nt & 1) ? 2 : 0] = *(uint32_t*)&pl01;
            afl[nt >> 1][(nt & 1) ? 3 : 1] = *(uint32_t*)&pl23;
        }

        // ---- AV: o += Ph@Vh + Ph@Vl + Pl@Vh, x4.trans V loads ----
        #pragma unroll
        for (int ks = 0; ks < 4; ks++) {
            #pragma unroll
            for (int dt2 = 0; dt2 < 4; dt2++) {
                uint32_t h4[4], l4[4];
                const uint32_t off = (uint32_t)((ks * 16 + (lane & 15)) * LDS * 2)
                                   + (uint32_t)(dt2 * 32) + (uint32_t)((lane >> 4) * 16);
                ldsm_x4t(h4[0], h4[1], h4[2], h4[3], sbVH + off);
                ldsm_x4t(l4[0], l4[1], l4[2], l4[3], sbVL + off);
                uint32_t v0h[2] = {h4[0], h4[1]}, v1h[2] = {h4[2], h4[3]};
                uint32_t v0l[2] = {l4[0], l4[1]}, v1l[2] = {l4[2], l4[3]};
                mma16816(oacc[2*dt2],   afh[ks], v0h);
                mma16816(oacc[2*dt2],   afh[ks], v0l);
                mma16816(oacc[2*dt2],   afl[ks], v0h);
                mma16816(oacc[2*dt2+1], afh[ks], v1h);
                mma16816(oacc[2*dt2+1], afh[ks], v1l);
                mma16816(oacc[2*dt2+1], afl[ks], v1h);
            }
        }
    }

    // ---- normalize and store (split bf16, feeds O-projection) ----
    rs0 += __shfl_xor_sync(0xFFFFFFFF, rs0, 1);
    rs0 += __shfl_xor_sync(0xFFFFFFFF, rs0, 2);
    rs1 += __shfl_xor_sync(0xFFFFFFFF, rs1, 1);
    rs1 += __shfl_xor_sync(0xFFFFFFFF, rs1, 2);
    const float inv0 = 1.0f / (rs0 + 1e-32f);
    const float inv1 = 1.0f / (rs1 + 1e-32f);

    const size_t ob0 = (size_t)(b * Qn + q0 + r0) * Dn + h * AD + (lane & 3) * 2;
    const size_t ob1 = ob0 + (size_t)8 * Dn;
    #pragma unroll
    for (int dt = 0; dt < 8; dt++) {
        const float a0 = oacc[dt][0] * inv0, a1 = oacc[dt][1] * inv0;
        const float a2 = oacc[dt][2] * inv1, a3 = oacc[dt][3] * inv1;
        __nv_bfloat16 h0 = __float2bfloat16(a0), h1 = __float2bfloat16(a1);
        __nv_bfloat16 h2 = __float2bfloat16(a2), h3 = __float2bfloat16(a3);
        __nv_bfloat162 hh0(h0, h1), hh1(h2, h3);
        __nv_bfloat162 ll0(__float2bfloat16(a0 - __bfloat162float(h0)),
                           __float2bfloat16(a1 - __bfloat162float(h1)));
        __nv_bfloat162 ll1(__float2bfloat16(a2 - __bfloat162float(h2)),
                           __float2bfloat16(a3 - __bfloat162float(h3)));
        *(uint32_t*)(obh + ob0 + dt * 8) = *(uint32_t*)&hh0;
        *(uint32_t*)(obl + ob0 + dt * 8) = *(uint32_t*)&ll0;
        *(uint32_t*)(obh + ob1 + dt * 8) = *(uint32_t*)&hh1;
        *(uint32_t*)(obl + ob1 + dt * 8) = *(uint32_t*)&ll1;
    }
}

// ---------------------------------------------------------------------------
extern "C" void kernel_launch(void* const* d_in, const int* in_sizes, int n_in,
                              void* d_out, int out_size) {
    const float* iQ    = (const float*)d_in[0];
    const float* iK    = (const float*)d_in[1];
    const int*   mask  = (const int*)d_in[2];
    const float* Wq    = (const float*)d_in[3];
    const float* Wkv   = (const float*)d_in[4];
    const float* Wo    = (const float*)d_in[5];
    const float* nbias = (const float*)d_in[6];
    float* out = (float*)d_out;

    __nv_bfloat16 *xqh,*xql,*xkh,*xkl,*obh,*obl,*wqh,*wql,*wkvh,*wkvl,*woh,*wol;
    __nv_bfloat16 *rqh,*rql,*kvh,*kvl;
    cudaGetSymbolAddress((void**)&xqh, g_xq_h);  cudaGetSymbolAddress((void**)&xql, g_xq_l);
    cudaGetSymbolAddress((void**)&xkh, g_xk_h);  cudaGetSymbolAddress((void**)&xkl, g_xk_l);
    cudaGetSymbolAddress((void**)&obh, g_ob_h);  cudaGetSymbolAddress((void**)&obl, g_ob_l);
    cudaGetSymbolAddress((void**)&wqh, g_wq_h);  cudaGetSymbolAddress((void**)&wql, g_wq_l);
    cudaGetSymbolAddress((void**)&wkvh, g_wkv_h);cudaGetSymbolAddress((void**)&wkvl, g_wkv_l);
    cudaGetSymbolAddress((void**)&woh, g_wo_h);  cudaGetSymbolAddress((void**)&wol, g_wo_l);
    cudaGetSymbolAddress((void**)&rqh, g_rq_h);  cudaGetSymbolAddress((void**)&rql, g_rq_l);
    cudaGetSymbolAddress((void**)&kvh, g_kv_h);  cudaGetSymbolAddress((void**)&kvl, g_kv_l);

    cudaFuncSetAttribute(gemm_mma_split, cudaFuncAttributeMaxDynamicSharedMemorySize, GEMM_SMEM);
    cudaFuncSetAttribute(attn_mma, cudaFuncAttributeMaxDynamicSharedMemorySize, ATTN_SMEM);

    // 0) split fp32 -> bf16 hi/lo (inputs + weights)
    cvt_split<<<(MQ*Dn)/1024, 256>>>(iQ,  xqh, xql, MQ*Dn);
    cvt_split<<<(MS*Dn)/1024, 256>>>(iK,  xkh, xkl, MS*Dn);
    cvt_split<<<(Dn*Dn)/1024, 256>>>(Wq,  wqh, wql, Dn*Dn);
    cvt_split<<<(2*Dn*Dn)/1024, 256>>>(Wkv, wkvh, wkvl, 2*Dn*Dn);
    cvt_split<<<(Dn*Dn)/1024, 256>>>(Wo,  woh, wol, Dn*Dn);

    // 1) projections -> split bf16 outputs
    gemm_mma_split<<<dim3(Dn/128,   MQ/128), 256, GEMM_SMEM>>>(xqh, xql, wqh,  wql,
                                                               nullptr, rqh, rql, MQ, Dn,   Dn);
    gemm_mma_split<<<dim3(2*Dn/128, MS/128), 256, GEMM_SMEM>>>(xkh, xkl, wkvh, wkvl,
                                                               nullptr, kvh, kvl, MS, 2*Dn, Dn);

    // 2) attention (tensor-core, double-buffered, split-bf16 out)
    attn_mma<<<dim3(Qn/128, B_*Hn), 256, ATTN_SMEM>>>(rqh, rql, kvh, kvl, mask, nbias, obh, obl);

    // 3) output projection (fp32 out)
    gemm_mma_split<<<dim3(Dn/128, MQ/128), 256, GEMM_SMEM>>>(obh, obl, woh, wol,
                                                             out, nullptr, nullptr, MQ, Dn, Dn);
}